// round 14
// baseline (speedup 1.0000x reference)
#include <cuda_runtime.h>
#include <cuda_bf16.h>

#define VOCAB 50257
#define BATCH 512
#define SEQ   512
#define TPB   128          // 4 tokens per thread — the confirmed-best config

__global__ __launch_bounds__(TPB) void bow_logits_kernel(
    const int*   __restrict__ ids,
    const float* __restrict__ W,     // [2, VOCAB]
    const float* __restrict__ bias,  // [2]
    float*       __restrict__ out)   // [BATCH, 2]
{
    const int row = blockIdx.x;
    const int tid = threadIdx.x;

    // Hoist bias for the reducing thread: in flight during the gather phase,
    // off the post-barrier critical path.
    float bias0 = 0.f, bias1 = 0.f;
    if (tid == 0) {
        bias0 = __ldg(bias + 0);
        bias1 = __ldg(bias + 1);
    }

    // 4 tokens per thread via one coalesced 16B load.
    const int4 t4 = *reinterpret_cast<const int4*>(ids + (row << 9) + tid * 4);

    const float* __restrict__ W0 = W;
    const float* __restrict__ W1 = W + VOCAB;

    // 8 independent front-batched gathers (pad id 0 contributes 0).
    float a0 = (t4.x != 0) ? __ldg(W0 + t4.x) : 0.f;
    float a1 = (t4.y != 0) ? __ldg(W0 + t4.y) : 0.f;
    float a2 = (t4.z != 0) ? __ldg(W0 + t4.z) : 0.f;
    float a3 = (t4.w != 0) ? __ldg(W0 + t4.w) : 0.f;
    float b0 = (t4.x != 0) ? __ldg(W1 + t4.x) : 0.f;
    float b1 = (t4.y != 0) ? __ldg(W1 + t4.y) : 0.f;
    float b2 = (t4.z != 0) ? __ldg(W1 + t4.z) : 0.f;
    float b3 = (t4.w != 0) ? __ldg(W1 + t4.w) : 0.f;

    float s0 = (a0 + a1) + (a2 + a3);
    float s1 = (b0 + b1) + (b2 + b3);

    // Warp reduction.
    #pragma unroll
    for (int o = 16; o > 0; o >>= 1) {
        s0 += __shfl_down_sync(0xffffffffu, s0, o);
        s1 += __shfl_down_sync(0xffffffffu, s1, o);
    }

    __shared__ float2 sm[TPB / 32];
    const int w = tid >> 5, l = tid & 31;
    if (l == 0) sm[w] = make_float2(s0, s1);
    __syncthreads();

    if (tid == 0) {
        float r0 = bias0, r1 = bias1;
        #pragma unroll
        for (int i = 0; i < TPB / 32; i++) { r0 += sm[i].x; r1 += sm[i].y; }
        float2 r;
        r.x = r0;
        r.y = r1;
        *reinterpret_cast<float2*>(out + row * 2) = r;
    }
}

extern "C" void kernel_launch(void* const* d_in, const int* in_sizes, int n_in,
                              void* d_out, int out_size) {
    const int*   ids  = (const int*)  d_in[0];  // input_ids [512, 512] int32
    const float* W    = (const float*)d_in[1];  // W [2, 50257] fp32
    const float* bias = (const float*)d_in[2];  // b [2] fp32
    float*       out  = (float*)d_out;          // logits [512, 2] fp32

    bow_logits_kernel<<<BATCH, TPB>>>(ids, W, bias, out);
}

// round 15
// speedup vs baseline: 1.1429x; 1.1429x over previous
#include <cuda_runtime.h>
#include <cuda_bf16.h>

#define VOCAB 50257
#define BATCH 512
#define SEQ   512
#define TPB   128          // 4 tokens per thread — the confirmed-best config

__global__ __launch_bounds__(TPB) void bow_logits_kernel(
    const int*   __restrict__ ids,
    const float* __restrict__ W,     // [2, VOCAB]
    const float* __restrict__ bias,  // [2]
    float*       __restrict__ out)   // [BATCH, 2]
{
    const int row = blockIdx.x;
    const int tid = threadIdx.x;

    // Hoist bias for the reducing thread: in flight during the gather phase,
    // off the post-barrier critical path.
    float bias0 = 0.f, bias1 = 0.f;
    if (tid == 0) {
        bias0 = __ldg(bias + 0);
        bias1 = __ldg(bias + 1);
    }

    // 4 tokens per thread via one coalesced 16B load.
    const int4 t4 = *reinterpret_cast<const int4*>(ids + (row << 9) + tid * 4);

    const float* __restrict__ W0 = W;
    const float* __restrict__ W1 = W + VOCAB;

    // 8 independent front-batched gathers (pad id 0 contributes 0).
    float a0 = (t4.x != 0) ? __ldg(W0 + t4.x) : 0.f;
    float a1 = (t4.y != 0) ? __ldg(W0 + t4.y) : 0.f;
    float a2 = (t4.z != 0) ? __ldg(W0 + t4.z) : 0.f;
    float a3 = (t4.w != 0) ? __ldg(W0 + t4.w) : 0.f;
    float b0 = (t4.x != 0) ? __ldg(W1 + t4.x) : 0.f;
    float b1 = (t4.y != 0) ? __ldg(W1 + t4.y) : 0.f;
    float b2 = (t4.z != 0) ? __ldg(W1 + t4.z) : 0.f;
    float b3 = (t4.w != 0) ? __ldg(W1 + t4.w) : 0.f;

    float s0 = (a0 + a1) + (a2 + a3);
    float s1 = (b0 + b1) + (b2 + b3);

    // Warp reduction.
    #pragma unroll
    for (int o = 16; o > 0; o >>= 1) {
        s0 += __shfl_down_sync(0xffffffffu, s0, o);
        s1 += __shfl_down_sync(0xffffffffu, s1, o);
    }

    __shared__ float2 sm[TPB / 32];
    const int w = tid >> 5, l = tid & 31;
    if (l == 0) sm[w] = make_float2(s0, s1);
    __syncthreads();

    if (tid == 0) {
        float r0 = bias0, r1 = bias1;
        #pragma unroll
        for (int i = 0; i < TPB / 32; i++) { r0 += sm[i].x; r1 += sm[i].y; }
        float2 r;
        r.x = r0;
        r.y = r1;
        *reinterpret_cast<float2*>(out + row * 2) = r;
    }
}

extern "C" void kernel_launch(void* const* d_in, const int* in_sizes, int n_in,
                              void* d_out, int out_size) {
    const int*   ids  = (const int*)  d_in[0];  // input_ids [512, 512] int32
    const float* W    = (const float*)d_in[1];  // W [2, 50257] fp32
    const float* bias = (const float*)d_in[2];  // b [2] fp32
    float*       out  = (float*)d_out;          // logits [512, 2] fp32

    bow_logits_kernel<<<BATCH, TPB>>>(ids, W, bias, out);
}